// round 11
// baseline (speedup 1.0000x reference)
#include <cuda_runtime.h>
#include <cuda_bf16.h>
#include <math.h>
#include <stdint.h>

#define BB 4
#define DM 1024
#define SS 2048
#define HH 16
#define HD 64
#define K2 2048   // GEMM rows: [hi x1024 | lo x1024]
#define AK2 128   // attention rows: [hi x64 | lo x64]

// ---------------- scratch (device globals; allocation-free) ----------------
__device__ __nv_bfloat16 g_xTbig[(size_t)BB * SS * K2];
__device__ __nv_bfloat16 g_Wqk[(size_t)2 * DM * K2];   // [Wq ; Wk] split rows
__device__ __nv_bfloat16 g_Wvb[(size_t)DM * K2];
__device__ __nv_bfloat16 g_Wob[(size_t)DM * K2];
__device__ __nv_bfloat16 g_Qs[(size_t)BB * HH * SS * AK2];  // [qh|ql] x0.125
__device__ __nv_bfloat16 g_Ks[(size_t)BB * HH * SS * AK2];  // [kh|kl]
__device__ __nv_bfloat16 g_Vt[(size_t)BB * HH * 32 * HD * AK2]; // V^T [vh|vl]
__device__ __nv_bfloat16 g_attbig[(size_t)BB * SS * K2];

// ---------------- helpers ----------------
__device__ __forceinline__ uint32_t smem_u32(const void* p) {
    uint32_t a;
    asm("{ .reg .u64 t; cvta.to.shared.u64 t, %1; cvt.u32.u64 %0, t; }" : "=r"(a) : "l"(p));
    return a;
}
__device__ __forceinline__ void cp16(uint32_t s, const void* g) {
    asm volatile("cp.async.cg.shared.global [%0], [%1], 16;" :: "r"(s), "l"(g) : "memory");
}
#define CP_COMMIT() asm volatile("cp.async.commit_group;" ::: "memory")
#define CP_WAIT1()  asm volatile("cp.async.wait_group 1;" ::: "memory")
#define CP_WAIT0()  asm volatile("cp.async.wait_group 0;" ::: "memory")

__device__ __forceinline__ void ldsm4(uint32_t* r, uint32_t addr) {
    asm volatile("ldmatrix.sync.aligned.m8n8.x4.shared.b16 {%0,%1,%2,%3}, [%4];"
                 : "=r"(r[0]), "=r"(r[1]), "=r"(r[2]), "=r"(r[3]) : "r"(addr));
}
__device__ __forceinline__ void mma16816(float* c, const uint32_t* a,
                                         uint32_t b0, uint32_t b1) {
    asm volatile("mma.sync.aligned.m16n8k16.row.col.f32.bf16.bf16.f32 "
                 "{%0,%1,%2,%3}, {%4,%5,%6,%7}, {%8,%9}, {%0,%1,%2,%3};"
                 : "+f"(c[0]), "+f"(c[1]), "+f"(c[2]), "+f"(c[3])
                 : "r"(a[0]), "r"(a[1]), "r"(a[2]), "r"(a[3]), "r"(b0), "r"(b1));
}
// round-based split (scalar paths, tiny kernels)
__device__ __forceinline__ void split2(float v, __nv_bfloat16& hi, __nv_bfloat16& lo) {
    hi = __float2bfloat16(v);
    lo = __float2bfloat16(v - __bfloat162float(hi));
}
// cheap truncation split (hot paths): hi = top 16 bits of fp32, lo = exact rest
__device__ __forceinline__ uint32_t packhi(float a, float b) {
    return __byte_perm(__float_as_uint(a), __float_as_uint(b), 0x7632);
}
__device__ __forceinline__ float lopart(float v) {
    return v - __uint_as_float(__float_as_uint(v) & 0xFFFF0000u);
}
__device__ __forceinline__ uint32_t packlo2(float l0, float l1) {
    uint32_t r;
    asm("cvt.rn.bf16x2.f32 %0, %1, %2;" : "=r"(r) : "f"(l1), "f"(l0));
    return r;  // l0 in low half
}

// ---------------------------------------------------------------------------
// Kernel 1: x[B,D,S] + PE -> xTbig rows [ah | al]
// ---------------------------------------------------------------------------
__global__ void pe_transpose_split(const float* __restrict__ x,
                                   __nv_bfloat16* __restrict__ out) {
    __shared__ float tile[32][33];
    int b = blockIdx.z;
    int d0 = blockIdx.y * 32, s0 = blockIdx.x * 32;
    int d = d0 + threadIdx.y, s = s0 + threadIdx.x;
    float denom = expf((float)(d & ~1) * (-9.210340371976184f / (float)DM));
    float ang = (float)s * denom;
    float pe = (d & 1) ? cosf(ang) : sinf(ang);
    tile[threadIdx.y][threadIdx.x] = x[((size_t)b * DM + d) * SS + s] + pe;
    __syncthreads();
    int s2 = s0 + threadIdx.y, d2 = d0 + threadIdx.x;
    float v = tile[threadIdx.x][threadIdx.y];
    __nv_bfloat16 hi, lo; split2(v, hi, lo);
    size_t base = ((size_t)b * SS + s2) * K2;
    out[base + d2] = hi;
    out[base + 1024 + d2] = lo;
}

// ---------------------------------------------------------------------------
// Kernel 1b: weight split -> rows [wh | wl]; Wq,Wk go into one buffer
// ---------------------------------------------------------------------------
__global__ void wsplit_kernel(const float* __restrict__ w0, const float* __restrict__ w1,
                              const float* __restrict__ w2, const float* __restrict__ w3,
                              __nv_bfloat16* oqk, __nv_bfloat16* o2, __nv_bfloat16* o3) {
    const float* src; __nv_bfloat16* dst;
    switch (blockIdx.y) {
        case 0: src = w0; dst = oqk; break;
        case 1: src = w1; dst = oqk + (size_t)DM * K2; break;
        case 2: src = w2; dst = o2; break;
        default: src = w3; dst = o3; break;
    }
    int idx = blockIdx.x * 256 + threadIdx.x;
    int n = idx >> 10, dcol = idx & 1023;
    __nv_bfloat16 hi, lo; split2(src[idx], hi, lo);
    size_t base = (size_t)n * K2;
    dst[base + dcol] = hi;
    dst[base + 1024 + dcol] = lo;
}

// ---------------------------------------------------------------------------
// Kernel 2: HMMA GEMM  C = ah·wh + al·wh + ah·wl  (three passes, shared frags)
// MODE template: 0 fused QK -> split rows (Q x0.125 -> outv, K -> outv2)
//                2 V^T [vh|vl], 3 fp32 [B,D,S]
// ---------------------------------------------------------------------------
#define STG 40960
#define GEMM_SMEM 81920

template <int MODE>
__global__ __launch_bounds__(256, 2)
void hmma_gemm(const __nv_bfloat16* __restrict__ A, const __nv_bfloat16* __restrict__ W,
               const float* __restrict__ bias, const float* __restrict__ bias2,
               void* __restrict__ outv, void* __restrict__ outv2) {
    extern __shared__ char smem[];
    const uint32_t sb = smem_u32(smem);
    const int tid = threadIdx.x, wid = tid >> 5, lane = tid & 31;
    const int wr = wid >> 1, wc = wid & 1;
    const int mBase = blockIdx.y * 128, nBase = blockIdx.x * 128;

    float acc[2][8][4];
#pragma unroll
    for (int i = 0; i < 2; i++)
#pragma unroll
        for (int j = 0; j < 8; j++)
#pragma unroll
            for (int r = 0; r < 4; r++) acc[i][j][r] = 0.f;

    const int r0 = tid >> 2, c4 = tid & 3;
    const __nv_bfloat16* gA = A + (size_t)(mBase + r0) * K2 + c4 * 8;
    const __nv_bfloat16* gW = W + (size_t)(nBase + r0) * K2 + c4 * 8;

#define LOAD_CHUNK(c, st)                                                     \
    do {                                                                      \
        uint32_t s0 = sb + (st) * STG + r0 * 80 + c4 * 16;                    \
        cp16(s0,                 gA + (c) * 32);                              \
        cp16(s0 + 64 * 80,       gA + (size_t)64 * K2 + (c) * 32);            \
        cp16(s0 + 10240,         gA + 1024 + (c) * 32);                       \
        cp16(s0 + 10240 + 64*80, gA + (size_t)64 * K2 + 1024 + (c) * 32);     \
        cp16(s0 + 20480,         gW + (c) * 32);                              \
        cp16(s0 + 20480 + 64*80, gW + (size_t)64 * K2 + (c) * 32);            \
        cp16(s0 + 30720,         gW + 1024 + (c) * 32);                       \
        cp16(s0 + 30720 + 64*80, gW + (size_t)64 * K2 + 1024 + (c) * 32);     \
        CP_COMMIT();                                                          \
    } while (0)

    LOAD_CHUNK(0, 0);
    LOAD_CHUNK(1, 1);

    const uint32_t aB = (wr * 32 + (lane & 15)) * 80 + (lane >> 4) * 16;
    const uint32_t bB = 20480 + (wc * 64 + (lane & 15)) * 80 + (lane >> 4) * 16;

    const int NCH = 1024 / 32;  // 32
    for (int c = 0; c < NCH; c++) {
        if (c == NCH - 1) CP_WAIT0(); else CP_WAIT1();
        __syncthreads();
        const uint32_t stg = sb + (c & 1) * STG;
#pragma unroll
        for (int ks = 0; ks < 2; ks++) {
            uint32_t ah[2][4], al[2][4], bh[4][4], bl[4][4];
            ldsm4(ah[0], stg + aB + ks * 32);
            ldsm4(ah[1], stg + aB + 16 * 80 + ks * 32);
            ldsm4(al[0], stg + aB + 10240 + ks * 32);
            ldsm4(al[1], stg + aB + 10240 + 16 * 80 + ks * 32);
#pragma unroll
            for (int j2 = 0; j2 < 4; j2++) {
                ldsm4(bh[j2], stg + bB + j2 * 16 * 80 + ks * 32);
                ldsm4(bl[j2], stg + bB + 10240 + j2 * 16 * 80 + ks * 32);
            }
#pragma unroll
            for (int mi = 0; mi < 2; mi++)
#pragma unroll
                for (int nj = 0; nj < 8; nj++) {
                    uint32_t b0 = bh[nj >> 1][nj & 1], b1 = bh[nj >> 1][(nj & 1) + 2];
                    mma16816(acc[mi][nj], ah[mi], b0, b1);
                    mma16816(acc[mi][nj], al[mi], b0, b1);
                    mma16816(acc[mi][nj], ah[mi],
                             bl[nj >> 1][nj & 1], bl[nj >> 1][(nj & 1) + 2]);
                }
        }
        __syncthreads();
        if (c + 2 < NCH) LOAD_CHUNK(c + 2, c & 1);
    }
#undef LOAD_CHUNK

    __syncthreads();
    float* ep = (float*)smem;
#pragma unroll
    for (int mi = 0; mi < 2; mi++)
#pragma unroll
        for (int nj = 0; nj < 8; nj++) {
            int row = wr * 32 + mi * 16 + (lane >> 2);
            int col = wc * 64 + nj * 8 + (lane & 3) * 2;
            ep[row * 129 + col] = acc[mi][nj][0];
            ep[row * 129 + col + 1] = acc[mi][nj][1];
            ep[(row + 8) * 129 + col] = acc[mi][nj][2];
            ep[(row + 8) * 129 + col + 1] = acc[mi][nj][3];
        }
    __syncthreads();

    if (MODE == 3) {
        float* out = (float*)outv;
        int nl = tid >> 1;
        int n = nBase + nl;
        float bn = bias[n];
#pragma unroll
        for (int ii = 0; ii < 16; ii++) {
            int sl = (tid & 1) * 64 + ii * 4;
            int m0 = mBase + sl, b = m0 >> 11, s = m0 & 2047;
            float4 v;
            v.x = ep[(sl + 0) * 129 + nl] + bn;
            v.y = ep[(sl + 1) * 129 + nl] + bn;
            v.z = ep[(sl + 2) * 129 + nl] + bn;
            v.w = ep[(sl + 3) * 129 + nl] + bn;
            *(float4*)&out[((size_t)b * DM + n) * SS + s] = v;
        }
    } else if (MODE == 2) {  // V^T: [bh, chunk, d, [vh64|vl64]]
        __nv_bfloat16* out = (__nv_bfloat16*)outv;
        int nl = tid >> 1, ch = tid & 1;
        int b = mBase >> 11, s0 = mBase & 2047;
        int h = (nBase + nl) >> 6, dd = (nBase + nl) & 63;
        float bn = bias[nBase + nl];
        size_t vb = (((size_t)(b * HH + h)) * 32 + (s0 >> 6) + ch) * (64 * AK2)
                    + (size_t)dd * AK2;
#pragma unroll
        for (int j = 0; j < 64; j += 2) {
            float v0 = ep[(ch * 64 + j) * 129 + nl] + bn;
            float v1 = ep[(ch * 64 + j + 1) * 129 + nl] + bn;
            *(uint32_t*)&out[vb + j] = packhi(v0, v1);
            *(uint32_t*)&out[vb + 64 + j] = packlo2(lopart(v0), lopart(v1));
        }
    } else {  // MODE 0: fused QK, rows [hi64|lo64]
        const bool isQ = (nBase < 1024);
        __nv_bfloat16* out = isQ ? (__nv_bfloat16*)outv : (__nv_bfloat16*)outv2;
        const float* bi = isQ ? bias : bias2;
        const int nOff = isQ ? nBase : nBase - 1024;
        const float sc = isQ ? 0.125f : 1.0f;
#pragma unroll
        for (int i = 0; i < 8; i++) {
            int r = (tid >> 4) + i * 16;
            int cc = (tid & 15) * 8;
            int m = mBase + r, b = m >> 11, s = m & 2047;
            int n = nOff + cc, h = n >> 6, dd = n & 63;
            size_t base = ((size_t)(b * HH + h) * SS + s) * AK2;
            uint32_t hp[4], lp[4];
#pragma unroll
            for (int j2 = 0; j2 < 4; j2++) {
                float v0 = (ep[r * 129 + cc + 2 * j2] + bi[n + 2 * j2]) * sc;
                float v1 = (ep[r * 129 + cc + 2 * j2 + 1] + bi[n + 2 * j2 + 1]) * sc;
                hp[j2] = packhi(v0, v1);
                lp[j2] = packlo2(lopart(v0), lopart(v1));
            }
            *(uint4*)&out[base + dd] = *(uint4*)&hp[0];
            *(uint4*)&out[base + 64 + dd] = *(uint4*)&lp[0];
        }
    }
}

// ---------------------------------------------------------------------------
// Kernel 3: HMMA flash attention v4 + cheap-split softmax datapath.
// CTA = (b,h) x 128 q; 8 warps x 16q; 2 CTAs/SM; register-resident split P.
// ---------------------------------------------------------------------------
#define APITCH 272
#define AQSZ (128 * APITCH)          // 34816
#define AKVT (64 * APITCH)           // 17408 per K (or V) tile
#define ASTG (2 * AKVT)              // 34816 per stage
#define ATTN_SMEM (AQSZ + 2 * ASTG)  // 104448

__device__ __forceinline__ void load_kv(uint32_t sb, int tid,
                                        const __nv_bfloat16* Kg,
                                        const __nv_bfloat16* Vg, int kt, int st) {
#pragma unroll
    for (int i = 0; i < 8; i++) {
        int idx = tid + i * 256;           // 0..2047
        int t = idx >= 1024;               // 0 = K, 1 = V
        int j = idx - t * 1024;
        int r = j >> 4, seg = j & 15;      // 16 segs of 16B = 256B/row
        uint32_t so = AQSZ + st * ASTG + t * AKVT + r * APITCH + seg * 16;
        size_t go = ((size_t)kt * 64 + r) * AK2 + seg * 8;
        cp16(sb + so, (t ? Vg : Kg) + go);
    }
    CP_COMMIT();
}

__global__ __launch_bounds__(256, 2)
void attn_hmma(const __nv_bfloat16* __restrict__ Qs,
               const __nv_bfloat16* __restrict__ Ks,
               const __nv_bfloat16* __restrict__ Vt,
               __nv_bfloat16* __restrict__ O) {
    extern __shared__ char smem[];
    const uint32_t sb = smem_u32(smem);
    const int tid = threadIdx.x, w = tid >> 5, lane = tid & 31;
    const int bh = blockIdx.y;
    const int q0 = blockIdx.x * 128;
    const __nv_bfloat16* Qg = Qs + ((size_t)bh * SS + q0) * AK2;
    const __nv_bfloat16* Kg = Ks + (size_t)bh * SS * AK2;
    const __nv_bfloat16* Vg = Vt + (size_t)bh * (32 * 64 * AK2);

#pragma unroll
    for (int i = 0; i < 8; i++) {
        int idx = tid + i * 256;
        int row = idx >> 4, seg = idx & 15;
        cp16(sb + row * APITCH + seg * 16, Qg + (size_t)row * AK2 + seg * 8);
    }
    load_kv(sb, tid, Kg, Vg, 0, 0);
    load_kv(sb, tid, Kg, Vg, 1, 1);

    float o[8][4];
    float mi[2] = {-1e30f, -1e30f}, li[2] = {0.f, 0.f};
#pragma unroll
    for (int nj = 0; nj < 8; nj++)
#pragma unroll
        for (int r = 0; r < 4; r++) o[nj][r] = 0.f;

    const int q4 = lane & 3;
    const int r1 = w * 16 + (lane >> 2);
    const uint32_t aQ = sb + (w * 16 + (lane & 15)) * APITCH + (lane >> 4) * 16;
    const uint32_t bKb = sb + AQSZ + (lane & 15) * APITCH + (lane >> 4) * 16;

    for (int kt = 0; kt < 32; kt++) {
        if (kt == 31) CP_WAIT0(); else CP_WAIT1();
        __syncthreads();
        const uint32_t stoff = (kt & 1) * ASTG;

        // --- S = qh·kh + ql·kh + qh·kl ---
        float sc[8][4];
#pragma unroll
        for (int nj = 0; nj < 8; nj++)
#pragma unroll
            for (int r = 0; r < 4; r++) sc[nj][r] = 0.f;
#pragma unroll
        for (int ks = 0; ks < 4; ks++) {
            uint32_t aqh[4], aql[4], bkh[4][4], bkl[4][4];
            ldsm4(aqh, aQ + ks * 32);
            ldsm4(aql, aQ + 128 + ks * 32);
#pragma unroll
            for (int j2 = 0; j2 < 4; j2++) {
                ldsm4(bkh[j2], bKb + stoff + j2 * 16 * APITCH + ks * 32);
                ldsm4(bkl[j2], bKb + stoff + 128 + j2 * 16 * APITCH + ks * 32);
            }
#pragma unroll
            for (int nj = 0; nj < 8; nj++) {
                uint32_t b0 = bkh[nj >> 1][nj & 1], b1 = bkh[nj >> 1][(nj & 1) + 2];
                mma16816(sc[nj], aqh, b0, b1);
                mma16816(sc[nj], aql, b0, b1);
                mma16816(sc[nj], aqh,
                         bkl[nj >> 1][nj & 1], bkl[nj >> 1][(nj & 1) + 2]);
            }
        }

        // --- online softmax; cheap-split P -> register A-fragments ---
        uint32_t aPhi[4][4], aPlo[4][4];
#pragma unroll
        for (int rr = 0; rr < 2; rr++) {
            float mx = -1e30f;
#pragma unroll
            for (int nj = 0; nj < 8; nj++)
                mx = fmaxf(mx, fmaxf(sc[nj][rr * 2], sc[nj][rr * 2 + 1]));
            mx = fmaxf(mx, __shfl_xor_sync(0xffffffffu, mx, 1));
            mx = fmaxf(mx, __shfl_xor_sync(0xffffffffu, mx, 2));
            float mn = fmaxf(mi[rr], mx);
            float rs = 0.f;
#pragma unroll
            for (int nj = 0; nj < 8; nj++) {
                float p0 = __expf(sc[nj][rr * 2] - mn);
                float p1 = __expf(sc[nj][rr * 2 + 1] - mn);
                rs += p0 + p1;
                aPhi[nj >> 1][(nj & 1) * 2 + rr] = packhi(p0, p1);
                aPlo[nj >> 1][(nj & 1) * 2 + rr] = packlo2(lopart(p0), lopart(p1));
            }
            rs += __shfl_xor_sync(0xffffffffu, rs, 1);
            rs += __shfl_xor_sync(0xffffffffu, rs, 2);
            float f = __expf(mi[rr] - mn);
            li[rr] = li[rr] * f + rs;
            mi[rr] = mn;
#pragma unroll
            for (int nj = 0; nj < 8; nj++) {
                o[nj][rr * 2] *= f;
                o[nj][rr * 2 + 1] *= f;
            }
        }

        // --- O += Phi·vh + Plo·vh + Phi·vl ---
        const uint32_t bVb = bKb + AKVT + stoff;
#pragma unroll
        for (int kk = 0; kk < 4; kk++) {
            uint32_t bvh[4][4], bvl[4][4];
#pragma unroll
            for (int j2 = 0; j2 < 4; j2++) {
                ldsm4(bvh[j2], bVb + j2 * 16 * APITCH + kk * 32);
                ldsm4(bvl[j2], bVb + 128 + j2 * 16 * APITCH + kk * 32);
            }
#pragma unroll
            for (int nj = 0; nj < 8; nj++) {
                uint32_t b0 = bvh[nj >> 1][nj & 1], b1 = bvh[nj >> 1][(nj & 1) + 2];
                mma16816(o[nj], aPhi[kk], b0, b1);
                mma16816(o[nj], aPlo[kk], b0, b1);
                mma16816(o[nj], aPhi[kk],
                         bvl[nj >> 1][nj & 1], bvl[nj >> 1][(nj & 1) + 2]);
            }
        }
        __syncthreads();
        if (kt + 2 < 32) load_kv(sb, tid, Kg, Vg, kt + 2, kt & 1);
    }

    // --- epilogue: normalize, emit [oh|ol] rows for Wo GEMM ---
    const int b_ = bh >> 4, h_ = bh & 15;
#pragma unroll
    for (int rr = 0; rr < 2; rr++) {
        float inv = 1.f / li[rr];
        size_t base = ((size_t)b_ * SS + q0 + r1 + rr * 8) * (size_t)K2;
#pragma unroll
        for (int nj = 0; nj < 8; nj++) {
            int d = nj * 8 + 2 * q4;
            float v0 = o[nj][rr * 2] * inv, v1 = o[nj][rr * 2 + 1] * inv;
            *(uint32_t*)&O[base + h_ * 64 + d] = packhi(v0, v1);
            *(uint32_t*)&O[base + 1024 + h_ * 64 + d] = packlo2(lopart(v0), lopart(v1));
        }
    }
}

// ---------------------------------------------------------------------------
extern "C" void kernel_launch(void* const* d_in, const int* in_sizes, int n_in,
                              void* d_out, int out_size) {
    const float* x  = (const float*)d_in[0];
    const float* Wq = (const float*)d_in[1];
    const float* bq = (const float*)d_in[2];
    const float* Wk = (const float*)d_in[3];
    const float* bk = (const float*)d_in[4];
    const float* Wv = (const float*)d_in[5];
    const float* bv = (const float*)d_in[6];
    const float* Wo = (const float*)d_in[7];
    const float* bo = (const float*)d_in[8];

    __nv_bfloat16 *xTb, *wqk, *wvb, *wob, *qs, *ks, *vt, *attb;
    cudaGetSymbolAddress((void**)&xTb, g_xTbig);
    cudaGetSymbolAddress((void**)&wqk, g_Wqk);
    cudaGetSymbolAddress((void**)&wvb, g_Wvb);
    cudaGetSymbolAddress((void**)&wob, g_Wob);
    cudaGetSymbolAddress((void**)&qs, g_Qs);
    cudaGetSymbolAddress((void**)&ks, g_Ks);
    cudaGetSymbolAddress((void**)&vt, g_Vt);
    cudaGetSymbolAddress((void**)&attb, g_attbig);

    pe_transpose_split<<<dim3(SS / 32, DM / 32, BB), dim3(32, 32)>>>(x, xTb);
    wsplit_kernel<<<dim3(DM * DM / 256, 4), 256>>>(Wq, Wk, Wv, Wo, wqk, wvb, wob);

    cudaFuncSetAttribute(hmma_gemm<0>, cudaFuncAttributeMaxDynamicSharedMemorySize, GEMM_SMEM);
    cudaFuncSetAttribute(hmma_gemm<2>, cudaFuncAttributeMaxDynamicSharedMemorySize, GEMM_SMEM);
    cudaFuncSetAttribute(hmma_gemm<3>, cudaFuncAttributeMaxDynamicSharedMemorySize, GEMM_SMEM);
    dim3 ggQK(2 * DM / 128, (BB * SS) / 128);  // (16, 64)
    dim3 gg(DM / 128, (BB * SS) / 128);        // (8, 64)
    hmma_gemm<0><<<ggQK, 256, GEMM_SMEM>>>(xTb, wqk, bq, bk, qs, ks);
    hmma_gemm<2><<<gg, 256, GEMM_SMEM>>>(xTb, wvb, bv, nullptr, vt, nullptr);

    cudaFuncSetAttribute(attn_hmma, cudaFuncAttributeMaxDynamicSharedMemorySize, ATTN_SMEM);
    attn_hmma<<<dim3(SS / 128, BB * HH), 256, ATTN_SMEM>>>(qs, ks, vt, attb);

    hmma_gemm<3><<<gg, 256, GEMM_SMEM>>>(attb, wob, bo, nullptr, d_out, nullptr);
}

// round 12
// speedup vs baseline: 1.0309x; 1.0309x over previous
#include <cuda_runtime.h>
#include <cuda_bf16.h>
#include <math.h>
#include <stdint.h>

#define BB 4
#define DM 1024
#define SS 2048
#define HH 16
#define HD 64
#define K2 2048   // GEMM rows: [hi x1024 | lo x1024]
#define AK2 128   // attention rows: [hi x64 | lo x64]

// ---------------- scratch (device globals; allocation-free) ----------------
__device__ __nv_bfloat16 g_xTbig[(size_t)BB * SS * K2];
__device__ __nv_bfloat16 g_Wqkv[(size_t)3 * DM * K2];  // [Wq ; Wk ; Wv] split rows
__device__ __nv_bfloat16 g_Wob[(size_t)DM * K2];
__device__ __nv_bfloat16 g_Qs[(size_t)BB * HH * SS * AK2];  // [qh|ql] x0.125
__device__ __nv_bfloat16 g_Ks[(size_t)BB * HH * SS * AK2];  // [kh|kl]
__device__ __nv_bfloat16 g_Vt[(size_t)BB * HH * 32 * HD * AK2]; // V^T [vh|vl]
__device__ __nv_bfloat16 g_attbig[(size_t)BB * SS * K2];

// ---------------- helpers ----------------
__device__ __forceinline__ uint32_t smem_u32(const void* p) {
    uint32_t a;
    asm("{ .reg .u64 t; cvta.to.shared.u64 t, %1; cvt.u32.u64 %0, t; }" : "=r"(a) : "l"(p));
    return a;
}
__device__ __forceinline__ void cp16(uint32_t s, const void* g) {
    asm volatile("cp.async.cg.shared.global [%0], [%1], 16;" :: "r"(s), "l"(g) : "memory");
}
#define CP_COMMIT() asm volatile("cp.async.commit_group;" ::: "memory")
#define CP_WAIT1()  asm volatile("cp.async.wait_group 1;" ::: "memory")
#define CP_WAIT0()  asm volatile("cp.async.wait_group 0;" ::: "memory")

__device__ __forceinline__ void ldsm4(uint32_t* r, uint32_t addr) {
    asm volatile("ldmatrix.sync.aligned.m8n8.x4.shared.b16 {%0,%1,%2,%3}, [%4];"
                 : "=r"(r[0]), "=r"(r[1]), "=r"(r[2]), "=r"(r[3]) : "r"(addr));
}
__device__ __forceinline__ void mma16816(float* c, const uint32_t* a,
                                         uint32_t b0, uint32_t b1) {
    asm volatile("mma.sync.aligned.m16n8k16.row.col.f32.bf16.bf16.f32 "
                 "{%0,%1,%2,%3}, {%4,%5,%6,%7}, {%8,%9}, {%0,%1,%2,%3};"
                 : "+f"(c[0]), "+f"(c[1]), "+f"(c[2]), "+f"(c[3])
                 : "r"(a[0]), "r"(a[1]), "r"(a[2]), "r"(a[3]), "r"(b0), "r"(b1));
}
// round-based split (scalar prep kernels)
__device__ __forceinline__ void split2(float v, __nv_bfloat16& hi, __nv_bfloat16& lo) {
    hi = __float2bfloat16(v);
    lo = __float2bfloat16(v - __bfloat162float(hi));
}
// cheap truncation split (hot paths): hi = top 16 bits of fp32, lo = exact rest
__device__ __forceinline__ uint32_t packhi(float a, float b) {
    return __byte_perm(__float_as_uint(a), __float_as_uint(b), 0x7632);
}
__device__ __forceinline__ float lopart(float v) {
    return v - __uint_as_float(__float_as_uint(v) & 0xFFFF0000u);
}
__device__ __forceinline__ uint32_t packlo2(float l0, float l1) {
    uint32_t r;
    asm("cvt.rn.bf16x2.f32 %0, %1, %2;" : "=r"(r) : "f"(l1), "f"(l0));
    return r;  // l0 in low half
}

// ---------------------------------------------------------------------------
// Kernel 1: x[B,D,S] + PE -> xTbig rows [ah | al]
// ---------------------------------------------------------------------------
__global__ void pe_transpose_split(const float* __restrict__ x,
                                   __nv_bfloat16* __restrict__ out) {
    __shared__ float tile[32][33];
    int b = blockIdx.z;
    int d0 = blockIdx.y * 32, s0 = blockIdx.x * 32;
    int d = d0 + threadIdx.y, s = s0 + threadIdx.x;
    float denom = expf((float)(d & ~1) * (-9.210340371976184f / (float)DM));
    float ang = (float)s * denom;
    float pe = (d & 1) ? cosf(ang) : sinf(ang);
    tile[threadIdx.y][threadIdx.x] = x[((size_t)b * DM + d) * SS + s] + pe;
    __syncthreads();
    int s2 = s0 + threadIdx.y, d2 = d0 + threadIdx.x;
    float v = tile[threadIdx.x][threadIdx.y];
    __nv_bfloat16 hi, lo; split2(v, hi, lo);
    size_t base = ((size_t)b * SS + s2) * K2;
    out[base + d2] = hi;
    out[base + 1024 + d2] = lo;
}

// ---------------------------------------------------------------------------
// Kernel 1b: weight split -> rows [wh | wl]; Wq,Wk,Wv into one buffer
// ---------------------------------------------------------------------------
__global__ void wsplit_kernel(const float* __restrict__ w0, const float* __restrict__ w1,
                              const float* __restrict__ w2, const float* __restrict__ w3,
                              __nv_bfloat16* oqkv, __nv_bfloat16* oo) {
    const float* src; __nv_bfloat16* dst;
    switch (blockIdx.y) {
        case 0: src = w0; dst = oqkv; break;
        case 1: src = w1; dst = oqkv + (size_t)DM * K2; break;
        case 2: src = w2; dst = oqkv + (size_t)2 * DM * K2; break;
        default: src = w3; dst = oo; break;
    }
    int idx = blockIdx.x * 256 + threadIdx.x;
    int n = idx >> 10, dcol = idx & 1023;
    __nv_bfloat16 hi, lo; split2(src[idx], hi, lo);
    size_t base = (size_t)n * K2;
    dst[base + dcol] = hi;
    dst[base + 1024 + dcol] = lo;
}

// ---------------------------------------------------------------------------
// Kernel 2: HMMA GEMM  C = ah·wh + al·wh + ah·wl  (three passes, shared frags)
// MODE 0: fused QKV (N=3072). nBase<1024 -> Q split x0.125; <2048 -> K split;
//         else V^T split with coalesced staged stores.
// MODE 3: fp32 [B,D,S] final output.
// ---------------------------------------------------------------------------
#define STG 40960
#define GEMM_SMEM 81920

template <int MODE>
__global__ __launch_bounds__(256, 2)
void hmma_gemm(const __nv_bfloat16* __restrict__ A, const __nv_bfloat16* __restrict__ W,
               const float* __restrict__ bias, const float* __restrict__ bias2,
               const float* __restrict__ bias3,
               void* __restrict__ outv, void* __restrict__ outv2,
               void* __restrict__ outv3) {
    extern __shared__ char smem[];
    const uint32_t sb = smem_u32(smem);
    const int tid = threadIdx.x, wid = tid >> 5, lane = tid & 31;
    const int wr = wid >> 1, wc = wid & 1;
    const int mBase = blockIdx.y * 128, nBase = blockIdx.x * 128;

    float acc[2][8][4];
#pragma unroll
    for (int i = 0; i < 2; i++)
#pragma unroll
        for (int j = 0; j < 8; j++)
#pragma unroll
            for (int r = 0; r < 4; r++) acc[i][j][r] = 0.f;

    const int r0 = tid >> 2, c4 = tid & 3;
    const __nv_bfloat16* gA = A + (size_t)(mBase + r0) * K2 + c4 * 8;
    const __nv_bfloat16* gW = W + (size_t)(nBase + r0) * K2 + c4 * 8;

#define LOAD_CHUNK(c, st)                                                     \
    do {                                                                      \
        uint32_t s0 = sb + (st) * STG + r0 * 80 + c4 * 16;                    \
        cp16(s0,                 gA + (c) * 32);                              \
        cp16(s0 + 64 * 80,       gA + (size_t)64 * K2 + (c) * 32);            \
        cp16(s0 + 10240,         gA + 1024 + (c) * 32);                       \
        cp16(s0 + 10240 + 64*80, gA + (size_t)64 * K2 + 1024 + (c) * 32);     \
        cp16(s0 + 20480,         gW + (c) * 32);                              \
        cp16(s0 + 20480 + 64*80, gW + (size_t)64 * K2 + (c) * 32);            \
        cp16(s0 + 30720,         gW + 1024 + (c) * 32);                       \
        cp16(s0 + 30720 + 64*80, gW + (size_t)64 * K2 + 1024 + (c) * 32);     \
        CP_COMMIT();                                                          \
    } while (0)

    LOAD_CHUNK(0, 0);
    LOAD_CHUNK(1, 1);

    const uint32_t aB = (wr * 32 + (lane & 15)) * 80 + (lane >> 4) * 16;
    const uint32_t bB = 20480 + (wc * 64 + (lane & 15)) * 80 + (lane >> 4) * 16;

    const int NCH = 1024 / 32;  // 32
    for (int c = 0; c < NCH; c++) {
        if (c == NCH - 1) CP_WAIT0(); else CP_WAIT1();
        __syncthreads();
        const uint32_t stg = sb + (c & 1) * STG;
#pragma unroll
        for (int ks = 0; ks < 2; ks++) {
            uint32_t ah[2][4], al[2][4], bh[4][4], bl[4][4];
            ldsm4(ah[0], stg + aB + ks * 32);
            ldsm4(ah[1], stg + aB + 16 * 80 + ks * 32);
            ldsm4(al[0], stg + aB + 10240 + ks * 32);
            ldsm4(al[1], stg + aB + 10240 + 16 * 80 + ks * 32);
#pragma unroll
            for (int j2 = 0; j2 < 4; j2++) {
                ldsm4(bh[j2], stg + bB + j2 * 16 * 80 + ks * 32);
                ldsm4(bl[j2], stg + bB + 10240 + j2 * 16 * 80 + ks * 32);
            }
#pragma unroll
            for (int mi = 0; mi < 2; mi++)
#pragma unroll
                for (int nj = 0; nj < 8; nj++) {
                    uint32_t b0 = bh[nj >> 1][nj & 1], b1 = bh[nj >> 1][(nj & 1) + 2];
                    mma16816(acc[mi][nj], ah[mi], b0, b1);
                    mma16816(acc[mi][nj], al[mi], b0, b1);
                    mma16816(acc[mi][nj], ah[mi],
                             bl[nj >> 1][nj & 1], bl[nj >> 1][(nj & 1) + 2]);
                }
        }
        __syncthreads();
        if (c + 2 < NCH) LOAD_CHUNK(c + 2, c & 1);
    }
#undef LOAD_CHUNK

    __syncthreads();
    float* ep = (float*)smem;
#pragma unroll
    for (int mi = 0; mi < 2; mi++)
#pragma unroll
        for (int nj = 0; nj < 8; nj++) {
            int row = wr * 32 + mi * 16 + (lane >> 2);
            int col = wc * 64 + nj * 8 + (lane & 3) * 2;
            ep[row * 129 + col] = acc[mi][nj][0];
            ep[row * 129 + col + 1] = acc[mi][nj][1];
            ep[(row + 8) * 129 + col] = acc[mi][nj][2];
            ep[(row + 8) * 129 + col + 1] = acc[mi][nj][3];
        }
    __syncthreads();

    if (MODE == 3) {
        float* out = (float*)outv;
        int nl = tid >> 1;
        int n = nBase + nl;
        float bn = bias[n];
#pragma unroll
        for (int ii = 0; ii < 16; ii++) {
            int sl = (tid & 1) * 64 + ii * 4;
            int m0 = mBase + sl, b = m0 >> 11, s = m0 & 2047;
            float4 v;
            v.x = ep[(sl + 0) * 129 + nl] + bn;
            v.y = ep[(sl + 1) * 129 + nl] + bn;
            v.z = ep[(sl + 2) * 129 + nl] + bn;
            v.w = ep[(sl + 3) * 129 + nl] + bn;
            *(float4*)&out[((size_t)b * DM + n) * SS + s] = v;
        }
    } else if (nBase >= 2048) {
        // V^T: [bh, chunk, d, [vh64|vl64]]; coalesced uint4 stores.
        __nv_bfloat16* out = (__nv_bfloat16*)outv3;
        int b = mBase >> 11, s0 = mBase & 2047;
#pragma unroll
        for (int it = 0; it < 8; it++) {
            int t = tid + it * 256;        // 0..2047
            int dl = t >> 4;               // local n (0..127)
            int rem = t & 15;
            int ch = rem >> 3, jb = (rem & 7) * 8;
            int n = nBase - 2048 + dl;
            int h = n >> 6, dd = n & 63;
            float bn = bias3[n];
            size_t vb = (((size_t)(b * HH + h)) * 32 + (s0 >> 6) + ch) * (64 * AK2)
                        + (size_t)dd * AK2;
            uint32_t hp[4], lp[4];
#pragma unroll
            for (int j2 = 0; j2 < 4; j2++) {
                float v0 = ep[(ch * 64 + jb + 2 * j2) * 129 + dl] + bn;
                float v1 = ep[(ch * 64 + jb + 2 * j2 + 1) * 129 + dl] + bn;
                hp[j2] = packhi(v0, v1);
                lp[j2] = packlo2(lopart(v0), lopart(v1));
            }
            *(uint4*)&out[vb + jb] = *(uint4*)&hp[0];
            *(uint4*)&out[vb + 64 + jb] = *(uint4*)&lp[0];
        }
    } else {
        // Q (nBase<1024, x0.125) / K: rows [hi64|lo64]
        const bool isQ = (nBase < 1024);
        __nv_bfloat16* out = isQ ? (__nv_bfloat16*)outv : (__nv_bfloat16*)outv2;
        const float* bi = isQ ? bias : bias2;
        const int nOff = isQ ? nBase : nBase - 1024;
        const float sc = isQ ? 0.125f : 1.0f;
#pragma unroll
        for (int i = 0; i < 8; i++) {
            int r = (tid >> 4) + i * 16;
            int cc = (tid & 15) * 8;
            int m = mBase + r, b = m >> 11, s = m & 2047;
            int n = nOff + cc, h = n >> 6, dd = n & 63;
            size_t base = ((size_t)(b * HH + h) * SS + s) * AK2;
            uint32_t hp[4], lp[4];
#pragma unroll
            for (int j2 = 0; j2 < 4; j2++) {
                float v0 = (ep[r * 129 + cc + 2 * j2] + bi[n + 2 * j2]) * sc;
                float v1 = (ep[r * 129 + cc + 2 * j2 + 1] + bi[n + 2 * j2 + 1]) * sc;
                hp[j2] = packhi(v0, v1);
                lp[j2] = packlo2(lopart(v0), lopart(v1));
            }
            *(uint4*)&out[base + dd] = *(uint4*)&hp[0];
            *(uint4*)&out[base + 64 + dd] = *(uint4*)&lp[0];
        }
    }
}

// ---------------------------------------------------------------------------
// Kernel 3: HMMA flash attention (unchanged from R10/11).
// CTA = (b,h) x 128 q; 8 warps x 16q; 2 CTAs/SM; register-resident split P.
// ---------------------------------------------------------------------------
#define APITCH 272
#define AQSZ (128 * APITCH)          // 34816
#define AKVT (64 * APITCH)           // 17408 per K (or V) tile
#define ASTG (2 * AKVT)              // 34816 per stage
#define ATTN_SMEM (AQSZ + 2 * ASTG)  // 104448

__device__ __forceinline__ void load_kv(uint32_t sb, int tid,
                                        const __nv_bfloat16* Kg,
                                        const __nv_bfloat16* Vg, int kt, int st) {
#pragma unroll
    for (int i = 0; i < 8; i++) {
        int idx = tid + i * 256;           // 0..2047
        int t = idx >= 1024;               // 0 = K, 1 = V
        int j = idx - t * 1024;
        int r = j >> 4, seg = j & 15;      // 16 segs of 16B = 256B/row
        uint32_t so = AQSZ + st * ASTG + t * AKVT + r * APITCH + seg * 16;
        size_t go = ((size_t)kt * 64 + r) * AK2 + seg * 8;
        cp16(sb + so, (t ? Vg : Kg) + go);
    }
    CP_COMMIT();
}

__global__ __launch_bounds__(256, 2)
void attn_hmma(const __nv_bfloat16* __restrict__ Qs,
               const __nv_bfloat16* __restrict__ Ks,
               const __nv_bfloat16* __restrict__ Vt,
               __nv_bfloat16* __restrict__ O) {
    extern __shared__ char smem[];
    const uint32_t sb = smem_u32(smem);
    const int tid = threadIdx.x, w = tid >> 5, lane = tid & 31;
    const int bh = blockIdx.y;
    const int q0 = blockIdx.x * 128;
    const __nv_bfloat16* Qg = Qs + ((size_t)bh * SS + q0) * AK2;
    const __nv_bfloat16* Kg = Ks + (size_t)bh * SS * AK2;
    const __nv_bfloat16* Vg = Vt + (size_t)bh * (32 * 64 * AK2);

#pragma unroll
    for (int i = 0; i < 8; i++) {
        int idx = tid + i * 256;
        int row = idx >> 4, seg = idx & 15;
        cp16(sb + row * APITCH + seg * 16, Qg + (size_t)row * AK2 + seg * 8);
    }
    load_kv(sb, tid, Kg, Vg, 0, 0);
    load_kv(sb, tid, Kg, Vg, 1, 1);

    float o[8][4];
    float mi[2] = {-1e30f, -1e30f}, li[2] = {0.f, 0.f};
#pragma unroll
    for (int nj = 0; nj < 8; nj++)
#pragma unroll
        for (int r = 0; r < 4; r++) o[nj][r] = 0.f;

    const int q4 = lane & 3;
    const int r1 = w * 16 + (lane >> 2);
    const uint32_t aQ = sb + (w * 16 + (lane & 15)) * APITCH + (lane >> 4) * 16;
    const uint32_t bKb = sb + AQSZ + (lane & 15) * APITCH + (lane >> 4) * 16;

    for (int kt = 0; kt < 32; kt++) {
        if (kt == 31) CP_WAIT0(); else CP_WAIT1();
        __syncthreads();
        const uint32_t stoff = (kt & 1) * ASTG;

        // --- S = qh·kh + ql·kh + qh·kl ---
        float sc[8][4];
#pragma unroll
        for (int nj = 0; nj < 8; nj++)
#pragma unroll
            for (int r = 0; r < 4; r++) sc[nj][r] = 0.f;
#pragma unroll
        for (int ks = 0; ks < 4; ks++) {
            uint32_t aqh[4], aql[4], bkh[4][4], bkl[4][4];
            ldsm4(aqh, aQ + ks * 32);
            ldsm4(aql, aQ + 128 + ks * 32);
#pragma unroll
            for (int j2 = 0; j2 < 4; j2++) {
                ldsm4(bkh[j2], bKb + stoff + j2 * 16 * APITCH + ks * 32);
                ldsm4(bkl[j2], bKb + stoff + 128 + j2 * 16 * APITCH + ks * 32);
            }
#pragma unroll
            for (int nj = 0; nj < 8; nj++) {
                uint32_t b0 = bkh[nj >> 1][nj & 1], b1 = bkh[nj >> 1][(nj & 1) + 2];
                mma16816(sc[nj], aqh, b0, b1);
                mma16816(sc[nj], aql, b0, b1);
                mma16816(sc[nj], aqh,
                         bkl[nj >> 1][nj & 1], bkl[nj >> 1][(nj & 1) + 2]);
            }
        }

        // --- online softmax; cheap-split P -> register A-fragments ---
        uint32_t aPhi[4][4], aPlo[4][4];
#pragma unroll
        for (int rr = 0; rr < 2; rr++) {
            float mx = -1e30f;
#pragma unroll
            for (int nj = 0; nj < 8; nj++)
                mx = fmaxf(mx, fmaxf(sc[nj][rr * 2], sc[nj][rr * 2 + 1]));
            mx = fmaxf(mx, __shfl_xor_sync(0xffffffffu, mx, 1));
            mx = fmaxf(mx, __shfl_xor_sync(0xffffffffu, mx, 2));
            float mn = fmaxf(mi[rr], mx);
            float rs = 0.f;
#pragma unroll
            for (int nj = 0; nj < 8; nj++) {
                float p0 = __expf(sc[nj][rr * 2] - mn);
                float p1 = __expf(sc[nj][rr * 2 + 1] - mn);
                rs += p0 + p1;
                aPhi[nj >> 1][(nj & 1) * 2 + rr] = packhi(p0, p1);
                aPlo[nj >> 1][(nj & 1) * 2 + rr] = packlo2(lopart(p0), lopart(p1));
            }
            rs += __shfl_xor_sync(0xffffffffu, rs, 1);
            rs += __shfl_xor_sync(0xffffffffu, rs, 2);
            float f = __expf(mi[rr] - mn);
            li[rr] = li[rr] * f + rs;
            mi[rr] = mn;
#pragma unroll
            for (int nj = 0; nj < 8; nj++) {
                o[nj][rr * 2] *= f;
                o[nj][rr * 2 + 1] *= f;
            }
        }

        // --- O += Phi·vh + Plo·vh + Phi·vl ---
        const uint32_t bVb = bKb + AKVT + stoff;
#pragma unroll
        for (int kk = 0; kk < 4; kk++) {
            uint32_t bvh[4][4], bvl[4][4];
#pragma unroll
            for (int j2 = 0; j2 < 4; j2++) {
                ldsm4(bvh[j2], bVb + j2 * 16 * APITCH + kk * 32);
                ldsm4(bvl[j2], bVb + 128 + j2 * 16 * APITCH + kk * 32);
            }
#pragma unroll
            for (int nj = 0; nj < 8; nj++) {
                uint32_t b0 = bvh[nj >> 1][nj & 1], b1 = bvh[nj >> 1][(nj & 1) + 2];
                mma16816(o[nj], aPhi[kk], b0, b1);
                mma16816(o[nj], aPlo[kk], b0, b1);
                mma16816(o[nj], aPhi[kk],
                         bvl[nj >> 1][nj & 1], bvl[nj >> 1][(nj & 1) + 2]);
            }
        }
        __syncthreads();
        if (kt + 2 < 32) load_kv(sb, tid, Kg, Vg, kt + 2, kt & 1);
    }

    // --- epilogue: normalize, emit [oh|ol] rows for Wo GEMM ---
    const int b_ = bh >> 4, h_ = bh & 15;
#pragma unroll
    for (int rr = 0; rr < 2; rr++) {
        float inv = 1.f / li[rr];
        size_t base = ((size_t)b_ * SS + q0 + r1 + rr * 8) * (size_t)K2;
#pragma unroll
        for (int nj = 0; nj < 8; nj++) {
            int d = nj * 8 + 2 * q4;
            float v0 = o[nj][rr * 2] * inv, v1 = o[nj][rr * 2 + 1] * inv;
            *(uint32_t*)&O[base + h_ * 64 + d] = packhi(v0, v1);
            *(uint32_t*)&O[base + 1024 + h_ * 64 + d] = packlo2(lopart(v0), lopart(v1));
        }
    }
}

// ---------------------------------------------------------------------------
extern "C" void kernel_launch(void* const* d_in, const int* in_sizes, int n_in,
                              void* d_out, int out_size) {
    const float* x  = (const float*)d_in[0];
    const float* Wq = (const float*)d_in[1];
    const float* bq = (const float*)d_in[2];
    const float* Wk = (const float*)d_in[3];
    const float* bk = (const float*)d_in[4];
    const float* Wv = (const float*)d_in[5];
    const float* bv = (const float*)d_in[6];
    const float* Wo = (const float*)d_in[7];
    const float* bo = (const float*)d_in[8];

    __nv_bfloat16 *xTb, *wqkv, *wob, *qs, *ks, *vt, *attb;
    cudaGetSymbolAddress((void**)&xTb, g_xTbig);
    cudaGetSymbolAddress((void**)&wqkv, g_Wqkv);
    cudaGetSymbolAddress((void**)&wob, g_Wob);
    cudaGetSymbolAddress((void**)&qs, g_Qs);
    cudaGetSymbolAddress((void**)&ks, g_Ks);
    cudaGetSymbolAddress((void**)&vt, g_Vt);
    cudaGetSymbolAddress((void**)&attb, g_attbig);

    pe_transpose_split<<<dim3(SS / 32, DM / 32, BB), dim3(32, 32)>>>(x, xTb);
    wsplit_kernel<<<dim3(DM * DM / 256, 4), 256>>>(Wq, Wk, Wv, Wo, wqkv, wob);

    cudaFuncSetAttribute(hmma_gemm<0>, cudaFuncAttributeMaxDynamicSharedMemorySize, GEMM_SMEM);
    cudaFuncSetAttribute(hmma_gemm<3>, cudaFuncAttributeMaxDynamicSharedMemorySize, GEMM_SMEM);
    dim3 ggQKV(3 * DM / 128, (BB * SS) / 128);  // (24, 64)
    dim3 gg(DM / 128, (BB * SS) / 128);         // (8, 64)
    hmma_gemm<0><<<ggQKV, 256, GEMM_SMEM>>>(xTb, wqkv, bq, bk, bv, qs, ks, vt);

    cudaFuncSetAttribute(attn_hmma, cudaFuncAttributeMaxDynamicSharedMemorySize, ATTN_SMEM);
    attn_hmma<<<dim3(SS / 128, BB * HH), 256, ATTN_SMEM>>>(qs, ks, vt, attb);

    hmma_gemm<3><<<gg, 256, GEMM_SMEM>>>(attb, wob, bo, nullptr, nullptr,
                                         d_out, nullptr, nullptr);
}